// round 5
// baseline (speedup 1.0000x reference)
#include <cuda_runtime.h>
#include <cuda_bf16.h>
#include <cstdint>
#include <math.h>

// ---------------- problem constants ----------------
#define NROWS 65536
#define DIN   512
#define HID   2048
#define DOUT  512
#define S_IN  0.04419417382415922f    // 1/sqrt(512)
#define S_H2  4.8828125e-4f           // (1/sqrt(2048))^2

// ---------------- scratch (static __device__, allowed) ----------------
__device__ __align__(256) __nv_bfloat16 g_Xh [(size_t)NROWS * DIN];
__device__ __align__(256) __nv_bfloat16 g_Xl [(size_t)NROWS * DIN];
__device__ __align__(256) __nv_bfloat16 g_W1th[(size_t)HID * DIN];   // [H][DIN]
__device__ __align__(256) __nv_bfloat16 g_W1tl[(size_t)HID * DIN];
__device__ __align__(256) __nv_bfloat16 g_W3th[(size_t)HID * DIN];
__device__ __align__(256) __nv_bfloat16 g_W3tl[(size_t)HID * DIN];
__device__ __align__(256) __nv_bfloat16 g_W2th[(size_t)DOUT * HID];  // [DOUT][H]
__device__ __align__(256) __nv_bfloat16 g_W2tl[(size_t)DOUT * HID];
__device__ __align__(256) __nv_bfloat16 g_W4th[(size_t)DOUT * HID];
__device__ __align__(256) __nv_bfloat16 g_W4tl[(size_t)DOUT * HID];
__device__ __align__(256) __nv_bfloat16 g_H1h[(size_t)NROWS * HID];
__device__ __align__(256) __nv_bfloat16 g_H1l[(size_t)NROWS * HID];
__device__ __align__(256) __nv_bfloat16 g_H2h[(size_t)NROWS * HID];
__device__ __align__(256) __nv_bfloat16 g_H2l[(size_t)NROWS * HID];

// ---------------- helpers ----------------
__device__ __forceinline__ uint32_t smem_u32(const void* p) {
    uint32_t a;
    asm("{ .reg .u64 t; cvta.to.shared.u64 t, %1; cvt.u32.u64 %0, t; }" : "=r"(a) : "l"(p));
    return a;
}
__device__ __forceinline__ void cp16(uint32_t d, const void* s) {
    asm volatile("cp.async.cg.shared.global [%0], [%1], 16;" :: "r"(d), "l"(s));
}
#define CP_COMMIT() asm volatile("cp.async.commit_group;" ::: "memory")
#define CP_WAIT1()  asm volatile("cp.async.wait_group 1;" ::: "memory")
#define CP_WAIT0()  asm volatile("cp.async.wait_group 0;" ::: "memory")

__device__ __forceinline__ void ldsm4(uint32_t (&r)[4], uint32_t addr) {
    asm volatile("ldmatrix.sync.aligned.m8n8.x4.shared.b16 {%0,%1,%2,%3}, [%4];"
                 : "=r"(r[0]), "=r"(r[1]), "=r"(r[2]), "=r"(r[3]) : "r"(addr));
}
__device__ __forceinline__ void mma16816(float (&d)[4], const uint32_t (&a)[4],
                                         uint32_t b0, uint32_t b1) {
    asm volatile(
        "mma.sync.aligned.m16n8k16.row.col.f32.bf16.bf16.f32 "
        "{%0,%1,%2,%3}, {%4,%5,%6,%7}, {%8,%9}, {%0,%1,%2,%3};"
        : "+f"(d[0]), "+f"(d[1]), "+f"(d[2]), "+f"(d[3])
        : "r"(a[0]), "r"(a[1]), "r"(a[2]), "r"(a[3]), "r"(b0), "r"(b1));
}

// SW64 swizzle for 64B-wide tile rows ([128][32] bf16 = 8KB tiles)
#define SWZ64(o) ((o) ^ (((o) >> 3) & 0x30))
#define TILE_B 8192

__device__ __forceinline__ uint32_t pack_bf2(__nv_bfloat16 a, __nv_bfloat16 b) {
    __nv_bfloat162 v(a, b);
    return *(uint32_t*)&v;
}

// ---------------- prep kernels ----------------
__global__ void split_x_kernel(const float* __restrict__ x) {
    size_t i = (size_t)blockIdx.x * 256 + threadIdx.x;          // float4 index
    float4 v = ((const float4*)x)[i];
    __nv_bfloat16 h[4], l[4];
    h[0] = __float2bfloat16_rn(v.x); l[0] = __float2bfloat16_rn(v.x - __bfloat162float(h[0]));
    h[1] = __float2bfloat16_rn(v.y); l[1] = __float2bfloat16_rn(v.y - __bfloat162float(h[1]));
    h[2] = __float2bfloat16_rn(v.z); l[2] = __float2bfloat16_rn(v.z - __bfloat162float(h[2]));
    h[3] = __float2bfloat16_rn(v.w); l[3] = __float2bfloat16_rn(v.w - __bfloat162float(h[3]));
    ((uint2*)g_Xh)[i] = *(uint2*)h;
    ((uint2*)g_Xl)[i] = *(uint2*)l;
}

// transpose in[K][N] -> out[N][K] with hi/lo split; block (32,8), grid (K/32, N/32)
__global__ void tsplit_kernel(const float* __restrict__ in, int which, int K, int N) {
    __nv_bfloat16 *oh, *ol;
    if (which == 0)      { oh = g_W1th; ol = g_W1tl; }
    else if (which == 1) { oh = g_W3th; ol = g_W3tl; }
    else if (which == 2) { oh = g_W2th; ol = g_W2tl; }
    else                 { oh = g_W4th; ol = g_W4tl; }
    __shared__ float t[32][33];
    int k0 = blockIdx.x * 32, n0 = blockIdx.y * 32;
    int tx = threadIdx.x, ty = threadIdx.y;
#pragma unroll
    for (int i = 0; i < 4; i++) {
        int k = ty + i * 8;
        t[k][tx] = in[(size_t)(k0 + k) * N + n0 + tx];
    }
    __syncthreads();
#pragma unroll
    for (int i = 0; i < 4; i++) {
        int n = ty + i * 8;
        float v = t[tx][n];
        __nv_bfloat16 h = __float2bfloat16_rn(v);
        oh[(size_t)(n0 + n) * K + k0 + tx] = h;
        ol[(size_t)(n0 + n) * K + k0 + tx] = __float2bfloat16_rn(v - __bfloat162float(h));
    }
}

// ---------------- stage 1: dual GEMM (K=512) + activations ----------------
// grid (16, 512): x = H-col tile, y = row tile; 256 threads; tiles [128][32] bf16
// 3-stage cp.async pipeline; epilogue staged through smem for coalesced stores.
#define S1_SMEM (3 * 6 * TILE_B)   // 147456
#define PSTRB 272                  // staged epilogue row stride (bytes), 17*16
__global__ __launch_bounds__(256, 1) void stage1_kernel(const float* __restrict__ bias) {
    extern __shared__ char smem[];
    const uint32_t sb = smem_u32(smem);
    const int tid = threadIdx.x, wid = tid >> 5, lane = tid & 31;
    const int warp_m = wid >> 1, warp_n = wid & 1;
    const int m0 = blockIdx.y * 128, n0 = blockIdx.x * 128;

    const int r_lane = (lane & 7) + ((lane >> 3) & 1) * 8;
    const int halfb  = ((lane >> 4) & 1) * 16;

    const __nv_bfloat16* srcs[6] = {
        g_Xh   + (size_t)m0 * DIN, g_Xl   + (size_t)m0 * DIN,
        g_W1th + (size_t)n0 * DIN, g_W1tl + (size_t)n0 * DIN,
        g_W3th + (size_t)n0 * DIN, g_W3tl + (size_t)n0 * DIN };

    float acc1[2][8][4], acc2[2][8][4];
#pragma unroll
    for (int m = 0; m < 2; m++)
#pragma unroll
        for (int nf = 0; nf < 8; nf++)
#pragma unroll
            for (int e = 0; e < 4; e++) { acc1[m][nf][e] = 0.f; acc2[m][nf][e] = 0.f; }

    auto load_chunk = [&](int c, int buf) {
        int k0 = c * 32;
#pragma unroll
        for (int t = 0; t < 6; t++) {
            uint32_t tb = sb + (uint32_t)(buf * 6 + t) * TILE_B;
            const __nv_bfloat16* base = srcs[t];
#pragma unroll
            for (int i = 0; i < 2; i++) {
                int s = tid + i * 256;
                int row = s >> 2, v = s & 3;
                cp16(tb + SWZ64(row * 64 + v * 16), base + (size_t)row * DIN + k0 + v * 8);
            }
        }
    };

    load_chunk(0, 0); CP_COMMIT();
    load_chunk(1, 1); CP_COMMIT();
    const int NCH = DIN / 32;   // 16
    for (int c = 0; c < NCH; c++) {
        if (c == NCH - 1) { CP_WAIT0(); } else { CP_WAIT1(); }
        __syncthreads();
        if (c + 2 < NCH) { load_chunk(c + 2, (c + 2) % 3); CP_COMMIT(); }

        const uint32_t tb0 = sb + (uint32_t)((c % 3) * 6) * TILE_B;
#pragma unroll
        for (int ks = 0; ks < 2; ks++) {
            const int kb = ks * 32;
            uint32_t Ah[2][4], Al[2][4];
#pragma unroll
            for (int m = 0; m < 2; m++) {
                uint32_t off = SWZ64((warp_m * 32 + m * 16 + r_lane) * 64 + kb + halfb);
                ldsm4(Ah[m], tb0 + off);
                ldsm4(Al[m], tb0 + TILE_B + off);
            }
#pragma unroll
            for (int p = 0; p < 4; p++) {
                uint32_t offB = SWZ64((warp_n * 64 + p * 16 + r_lane) * 64 + kb + halfb);
                uint32_t b1h[4], b1l[4], b2h[4], b2l[4];
                ldsm4(b1h, tb0 + 2 * TILE_B + offB);
                ldsm4(b1l, tb0 + 3 * TILE_B + offB);
                ldsm4(b2h, tb0 + 4 * TILE_B + offB);
                ldsm4(b2l, tb0 + 5 * TILE_B + offB);
#pragma unroll
                for (int e = 0; e < 2; e++) {
                    const int nf = p * 2 + e;
#pragma unroll
                    for (int m = 0; m < 2; m++) {
                        mma16816(acc1[m][nf], Ah[m], b1h[e], b1h[2 + e]);
                        mma16816(acc1[m][nf], Ah[m], b1l[e], b1l[2 + e]);
                        mma16816(acc1[m][nf], Al[m], b1h[e], b1h[2 + e]);
                        mma16816(acc2[m][nf], Ah[m], b2h[e], b2h[2 + e]);
                        mma16816(acc2[m][nf], Ah[m], b2l[e], b2l[2 + e]);
                        mma16816(acc2[m][nf], Al[m], b2h[e], b2h[2 + e]);
                    }
                }
            }
        }
    }

    // ---- epilogue: activations + hi/lo split, staged via smem ----
    __syncthreads();   // all warps done with load buffers; smem reusable
    const int g = lane >> 2, t4 = lane & 3;
#pragma unroll
    for (int m = 0; m < 2; m++) {
#pragma unroll
        for (int nf = 0; nf < 8; nf++) {
            const int cl = warp_n * 64 + nf * 8 + t4 * 2;
            const float b0 = __ldg(bias + n0 + cl), b1v = __ldg(bias + n0 + cl + 1);
#pragma unroll
            for (int h = 0; h < 2; h++) {
                const int rl = warp_m * 32 + m * 16 + g + h * 8;
                float s1a = acc1[m][nf][h * 2 + 0] * S_IN + b0;
                float s1b = acc1[m][nf][h * 2 + 1] * S_IN + b1v;
                float h1a = __cosf(s1a), h1b = __cosf(s1b);
                float z0 = acc2[m][nf][h * 2 + 0] * S_IN;
                float z1 = acc2[m][nf][h * 2 + 1] * S_IN;
                float h2a = 1.f / (1.f + __expf(-z0));
                float h2b = 1.f / (1.f + __expf(-z1));

                __nv_bfloat16 a1h = __float2bfloat16_rn(h1a);
                __nv_bfloat16 c1h = __float2bfloat16_rn(h1b);
                __nv_bfloat16 a1l = __float2bfloat16_rn(h1a - __bfloat162float(a1h));
                __nv_bfloat16 c1l = __float2bfloat16_rn(h1b - __bfloat162float(c1h));
                __nv_bfloat16 a2h = __float2bfloat16_rn(h2a);
                __nv_bfloat16 c2h = __float2bfloat16_rn(h2b);
                __nv_bfloat16 a2l = __float2bfloat16_rn(h2a - __bfloat162float(a2h));
                __nv_bfloat16 c2l = __float2bfloat16_rn(h2b - __bfloat162float(c2h));

                uint32_t off = (uint32_t)rl * PSTRB + cl * 2;
                *(uint32_t*)(smem + 0 * 34816 + off) = pack_bf2(a1h, c1h);
                *(uint32_t*)(smem + 1 * 34816 + off) = pack_bf2(a1l, c1l);
                *(uint32_t*)(smem + 2 * 34816 + off) = pack_bf2(a2h, c2h);
                *(uint32_t*)(smem + 3 * 34816 + off) = pack_bf2(a2l, c2l);
            }
        }
    }
    __syncthreads();

    __nv_bfloat16* outs[4] = { g_H1h, g_H1l, g_H2h, g_H2l };
#pragma unroll
    for (int a = 0; a < 4; a++) {
        __nv_bfloat16* op = outs[a];
#pragma unroll
        for (int pass = 0; pass < 8; pass++) {
            int idx = pass * 2048 + tid * 8;       // bf16 element index in 128x128 tile
            int row = idx >> 7, col = idx & 127;
            uint4 v = *(const uint4*)(smem + a * 34816 + (uint32_t)row * PSTRB + col * 2);
            *(uint4*)(op + (size_t)(m0 + row) * HID + n0 + col) = v;
        }
    }
}

// ---------------- stage 2: fused dual GEMM (K=2048) + product ----------------
// grid (4, 512): x = DOUT col tile, y = row tile; 3-stage pipeline
#define S2_SMEM (3 * 8 * TILE_B)   // 196608
__global__ __launch_bounds__(256, 1) void stage2_kernel(float* __restrict__ out) {
    extern __shared__ char smem[];
    const uint32_t sb = smem_u32(smem);
    const int tid = threadIdx.x, wid = tid >> 5, lane = tid & 31;
    const int warp_m = wid >> 1, warp_n = wid & 1;
    const int m0 = blockIdx.y * 128, c0 = blockIdx.x * 128;

    const int r_lane = (lane & 7) + ((lane >> 3) & 1) * 8;
    const int halfb  = ((lane >> 4) & 1) * 16;

    const __nv_bfloat16* srcs[8] = {
        g_H1h  + (size_t)m0 * HID, g_H1l  + (size_t)m0 * HID,
        g_H2h  + (size_t)m0 * HID, g_H2l  + (size_t)m0 * HID,
        g_W2th + (size_t)c0 * HID, g_W2tl + (size_t)c0 * HID,
        g_W4th + (size_t)c0 * HID, g_W4tl + (size_t)c0 * HID };

    float acc1[2][8][4], acc2[2][8][4];
#pragma unroll
    for (int m = 0; m < 2; m++)
#pragma unroll
        for (int nf = 0; nf < 8; nf++)
#pragma unroll
            for (int e = 0; e < 4; e++) { acc1[m][nf][e] = 0.f; acc2[m][nf][e] = 0.f; }

    auto load_chunk = [&](int c, int buf) {
        int k0 = c * 32;
#pragma unroll
        for (int t = 0; t < 8; t++) {
            uint32_t tb = sb + (uint32_t)(buf * 8 + t) * TILE_B;
            const __nv_bfloat16* base = srcs[t];
#pragma unroll
            for (int i = 0; i < 2; i++) {
                int s = tid + i * 256;
                int row = s >> 2, v = s & 3;
                cp16(tb + SWZ64(row * 64 + v * 16), base + (size_t)row * HID + k0 + v * 8);
            }
        }
    };

    load_chunk(0, 0); CP_COMMIT();
    load_chunk(1, 1); CP_COMMIT();
    const int NCH = HID / 32;   // 64
    for (int c = 0; c < NCH; c++) {
        if (c == NCH - 1) { CP_WAIT0(); } else { CP_WAIT1(); }
        __syncthreads();
        if (c + 2 < NCH) { load_chunk(c + 2, (c + 2) % 3); CP_COMMIT(); }

        const uint32_t tb0 = sb + (uint32_t)((c % 3) * 8) * TILE_B;
#pragma unroll
        for (int ks = 0; ks < 2; ks++) {
            const int kb = ks * 32;
            uint32_t A1h[2][4], A1l[2][4], A2h[2][4], A2l[2][4];
#pragma unroll
            for (int m = 0; m < 2; m++) {
                uint32_t off = SWZ64((warp_m * 32 + m * 16 + r_lane) * 64 + kb + halfb);
                ldsm4(A1h[m], tb0 + off);
                ldsm4(A1l[m], tb0 + TILE_B + off);
                ldsm4(A2h[m], tb0 + 2 * TILE_B + off);
                ldsm4(A2l[m], tb0 + 3 * TILE_B + off);
            }
#pragma unroll
            for (int p = 0; p < 4; p++) {
                uint32_t offB = SWZ64((warp_n * 64 + p * 16 + r_lane) * 64 + kb + halfb);
                uint32_t b1h[4], b1l[4], b2h[4], b2l[4];
                ldsm4(b1h, tb0 + 4 * TILE_B + offB);
                ldsm4(b1l, tb0 + 5 * TILE_B + offB);
                ldsm4(b2h, tb0 + 6 * TILE_B + offB);
                ldsm4(b2l, tb0 + 7 * TILE_B + offB);
#pragma unroll
                for (int e = 0; e < 2; e++) {
                    const int nf = p * 2 + e;
#pragma unroll
                    for (int m = 0; m < 2; m++) {
                        mma16816(acc1[m][nf], A1h[m], b1h[e], b1h[2 + e]);
                        mma16816(acc1[m][nf], A1h[m], b1l[e], b1l[2 + e]);
                        mma16816(acc1[m][nf], A1l[m], b1h[e], b1h[2 + e]);
                        mma16816(acc2[m][nf], A2h[m], b2h[e], b2h[2 + e]);
                        mma16816(acc2[m][nf], A2h[m], b2l[e], b2l[2 + e]);
                        mma16816(acc2[m][nf], A2l[m], b2h[e], b2h[2 + e]);
                    }
                }
            }
        }
    }

    // epilogue: out = acc1*acc2*S_H2 (fp32), 32B-sector-aligned float2 stores
    const int g = lane >> 2, t4 = lane & 3;
#pragma unroll
    for (int m = 0; m < 2; m++) {
#pragma unroll
        for (int nf = 0; nf < 8; nf++) {
            const int col = c0 + warp_n * 64 + nf * 8 + t4 * 2;
#pragma unroll
            for (int h = 0; h < 2; h++) {
                const int row = m0 + warp_m * 32 + m * 16 + g + h * 8;
                float2 o;
                o.x = acc1[m][nf][h * 2 + 0] * acc2[m][nf][h * 2 + 0] * S_H2;
                o.y = acc1[m][nf][h * 2 + 1] * acc2[m][nf][h * 2 + 1] * S_H2;
                *(float2*)(out + (size_t)row * DOUT + col) = o;
            }
        }
    }
}

// ---------------- launch ----------------
// Inputs (metadata order): x, W_rff1, bias, W_rff2, W_sig1, W_sig2
extern "C" void kernel_launch(void* const* d_in, const int* in_sizes, int n_in,
                              void* d_out, int out_size)
{
    (void)in_sizes; (void)n_in; (void)out_size;
    const float* x    = (const float*)d_in[0];
    const float* W1   = (const float*)d_in[1];
    const float* bias = (const float*)d_in[2];
    const float* W2   = (const float*)d_in[3];
    const float* W3   = (const float*)d_in[4];
    const float* W4   = (const float*)d_in[5];
    float* out = (float*)d_out;

    cudaFuncSetAttribute(stage1_kernel, cudaFuncAttributeMaxDynamicSharedMemorySize, S1_SMEM);
    cudaFuncSetAttribute(stage2_kernel, cudaFuncAttributeMaxDynamicSharedMemorySize, S2_SMEM);

    split_x_kernel<<<(NROWS * DIN / 4) / 256, 256>>>(x);
    // W1, W3: [DIN][HID] -> [HID][DIN]
    tsplit_kernel<<<dim3(DIN / 32, HID / 32), dim3(32, 8)>>>(W1, 0, DIN, HID);
    tsplit_kernel<<<dim3(DIN / 32, HID / 32), dim3(32, 8)>>>(W3, 1, DIN, HID);
    // W2, W4: [HID][DOUT] -> [DOUT][HID]
    tsplit_kernel<<<dim3(HID / 32, DOUT / 32), dim3(32, 8)>>>(W2, 2, HID, DOUT);
    tsplit_kernel<<<dim3(HID / 32, DOUT / 32), dim3(32, 8)>>>(W4, 3, HID, DOUT);

    stage1_kernel<<<dim3(HID / 128, NROWS / 128), 256, S1_SMEM>>>(bias);
    stage2_kernel<<<dim3(DOUT / 128, NROWS / 128), 256, S2_SMEM>>>(out);
}

// round 10
// speedup vs baseline: 1.6568x; 1.6568x over previous
#include <cuda_runtime.h>
#include <cstdint>
#include <math.h>

// ---------------- problem constants ----------------
#define NROWS 65536
#define DIN   512
#define HID   2048
#define DOUT  512
#define S_IN   0.04419417382415922f   // 1/sqrt(512)
#define S_H2   4.8828125e-4f          // (1/sqrt(2048))^2
#define INV128 0.0078125f
#define INV127 0.007874015748031496f
#define INV127SQ 6.200012400024800e-5f  // (1/127)^2

// ---------------- scratch (static __device__, allowed) ----------------
__device__ __align__(256) int8_t g_Xq0[(size_t)NROWS * DIN];
__device__ __align__(256) int8_t g_Xq1[(size_t)NROWS * DIN];
__device__ float g_sX[NROWS];
__device__ __align__(256) int8_t g_W1q0[(size_t)HID * DIN];   // W1^T [H][DIN]
__device__ __align__(256) int8_t g_W1q1[(size_t)HID * DIN];
__device__ __align__(256) int8_t g_W3q0[(size_t)HID * DIN];
__device__ __align__(256) int8_t g_W3q1[(size_t)HID * DIN];
__device__ __align__(256) int8_t g_W2q0[(size_t)DOUT * HID];  // W2^T [DOUT][H]
__device__ __align__(256) int8_t g_W2q1[(size_t)DOUT * HID];
__device__ __align__(256) int8_t g_W4q0[(size_t)DOUT * HID];
__device__ __align__(256) int8_t g_W4q1[(size_t)DOUT * HID];
__device__ float g_sW1[HID];
__device__ float g_sW3[HID];
__device__ float g_sW2[DOUT];
__device__ float g_sW4[DOUT];
__device__ __align__(256) int8_t g_H1q0[(size_t)NROWS * HID];
__device__ __align__(256) int8_t g_H1q1[(size_t)NROWS * HID];
__device__ __align__(256) int8_t g_H2q0[(size_t)NROWS * HID];
__device__ __align__(256) int8_t g_H2q1[(size_t)NROWS * HID];

// ---------------- helpers ----------------
__device__ __forceinline__ uint32_t smem_u32(const void* p) {
    uint32_t a;
    asm("{ .reg .u64 t; cvta.to.shared.u64 t, %1; cvt.u32.u64 %0, t; }" : "=r"(a) : "l"(p));
    return a;
}
__device__ __forceinline__ void cp16(uint32_t d, const void* s) {
    asm volatile("cp.async.cg.shared.global [%0], [%1], 16;" :: "r"(d), "l"(s));
}
#define CP_COMMIT() asm volatile("cp.async.commit_group;" ::: "memory")
#define CP_WAIT1()  asm volatile("cp.async.wait_group 1;" ::: "memory")
#define CP_WAIT0()  asm volatile("cp.async.wait_group 0;" ::: "memory")

__device__ __forceinline__ void ldsm4(uint32_t (&r)[4], uint32_t addr) {
    asm volatile("ldmatrix.sync.aligned.m8n8.x4.shared.b16 {%0,%1,%2,%3}, [%4];"
                 : "=r"(r[0]), "=r"(r[1]), "=r"(r[2]), "=r"(r[3]) : "r"(addr));
}
// int8 MMA: m16n8k32, s8 x s8 -> s32
__device__ __forceinline__ void imma(int (&d)[4], const uint32_t (&a)[4],
                                     uint32_t b0, uint32_t b1) {
    asm volatile(
        "mma.sync.aligned.m16n8k32.row.col.s32.s8.s8.s32 "
        "{%0,%1,%2,%3}, {%4,%5,%6,%7}, {%8,%9}, {%0,%1,%2,%3};"
        : "+r"(d[0]), "+r"(d[1]), "+r"(d[2]), "+r"(d[3])
        : "r"(a[0]), "r"(a[1]), "r"(a[2]), "r"(a[3]), "r"(b0), "r"(b1));
}

// SW64 swizzle for 64B-wide rows; [128][64] int8 tile = 8KB, [64][64] = 4KB
#define SWZ64(o) ((o) ^ (((o) >> 3) & 0x30))

// ---------------- prep: quantize X (per-row scale, 2-level int8) ----------------
__global__ void quant_x_kernel(const float* __restrict__ x) {
    int wrow = blockIdx.x * 8 + (threadIdx.x >> 5);
    int lane = threadIdx.x & 31;
    const float4* xr = (const float4*)(x + (size_t)wrow * DIN);
    float4 v[4];
    float m = 0.f;
#pragma unroll
    for (int i = 0; i < 4; i++) {
        v[i] = xr[lane + i * 32];
        m = fmaxf(m, fmaxf(fmaxf(fabsf(v[i].x), fabsf(v[i].y)),
                           fmaxf(fabsf(v[i].z), fabsf(v[i].w))));
    }
#pragma unroll
    for (int o = 16; o; o >>= 1) m = fmaxf(m, __shfl_xor_sync(0xFFFFFFFFu, m, o));
    m = fmaxf(m, 1e-20f);
    float inv = 127.f / m;
    if (lane == 0) g_sX[wrow] = m * INV127;
#pragma unroll
    for (int i = 0; i < 4; i++) {
        float t0 = v[i].x * inv, t1 = v[i].y * inv, t2 = v[i].z * inv, t3 = v[i].w * inv;
        int a0 = __float2int_rn(t0), a1 = __float2int_rn(t1);
        int a2 = __float2int_rn(t2), a3 = __float2int_rn(t3);
        char4 q0 = make_char4((char)a0, (char)a1, (char)a2, (char)a3);
        char4 q1 = make_char4((char)__float2int_rn((t0 - a0) * 128.f),
                              (char)__float2int_rn((t1 - a1) * 128.f),
                              (char)__float2int_rn((t2 - a2) * 128.f),
                              (char)__float2int_rn((t3 - a3) * 128.f));
        ((char4*)g_Xq0)[(size_t)wrow * (DIN / 4) + lane + i * 32] = q0;
        ((char4*)g_Xq1)[(size_t)wrow * (DIN / 4) + lane + i * 32] = q1;
    }
}

// ---------------- prep: weight scales + transpose-quantize ----------------
__global__ void zero_scales_kernel() {
    int i = blockIdx.x * 256 + threadIdx.x;
    if (i < HID)  { g_sW1[i] = 0.f; g_sW3[i] = 0.f; }
    if (i < DOUT) { g_sW2[i] = 0.f; g_sW4[i] = 0.f; }
}
__global__ void wcolmax_kernel(const float* __restrict__ in, int which, int K, int N) {
    float* sc = (which == 0) ? g_sW1 : (which == 1) ? g_sW3 : (which == 2) ? g_sW2 : g_sW4;
    int n = blockIdx.x * 256 + threadIdx.x;
    int kn = K / 8;
    const float* p = in + (size_t)blockIdx.y * kn * N + n;
    float m = 0.f;
#pragma unroll 8
    for (int k = 0; k < kn; k++) m = fmaxf(m, fabsf(p[(size_t)k * N]));
    atomicMax((unsigned int*)&sc[n], __float_as_uint(m));
}
// transpose in[K][N] -> q0/q1 [N][K]
__global__ void wquant_kernel(const float* __restrict__ in, int which, int K, int N) {
    int8_t* q0o; int8_t* q1o; const float* sc;
    if (which == 0)      { q0o = g_W1q0; q1o = g_W1q1; sc = g_sW1; }
    else if (which == 1) { q0o = g_W3q0; q1o = g_W3q1; sc = g_sW3; }
    else if (which == 2) { q0o = g_W2q0; q1o = g_W2q1; sc = g_sW2; }
    else                 { q0o = g_W4q0; q1o = g_W4q1; sc = g_sW4; }
    __shared__ float t[32][33];
    int k0 = blockIdx.x * 32, n0 = blockIdx.y * 32;
    int tx = threadIdx.x, ty = threadIdx.y;
#pragma unroll
    for (int i = 0; i < 4; i++)
        t[ty + i * 8][tx] = in[(size_t)(k0 + ty + i * 8) * N + n0 + tx];
    __syncthreads();
#pragma unroll
    for (int i = 0; i < 4; i++) {
        int n = n0 + ty + i * 8;
        float inv = 127.f / fmaxf(sc[n], 1e-20f);
        float v = t[tx][ty + i * 8] * inv;
        int a = __float2int_rn(v);
        q0o[(size_t)n * K + k0 + tx] = (int8_t)a;
        q1o[(size_t)n * K + k0 + tx] = (int8_t)__float2int_rn((v - a) * 128.f);
    }
}

// ---------------- stage 1: dual int8 GEMM (K=512) + activations ----------------
// grid (HID/64=32, NROWS/128=512), 256 threads (8 warps, 4m x 2n), warp tile 32x32
// buffer = A0,A1 (8KB each) + B0..B3 (4KB each) = 32KB; 3 buffers
#define S1_SMEM (3 * 32768)
__global__ __launch_bounds__(256, 1) void stage1_kernel(const float* __restrict__ bias) {
    extern __shared__ char smem[];
    const uint32_t sb = smem_u32(smem);
    const int tid = threadIdx.x, wid = tid >> 5, lane = tid & 31;
    const int warp_m = wid & 3, warp_n = wid >> 2;
    const int m0 = blockIdx.y * 128, n0 = blockIdx.x * 64;
    const int r_lane = lane & 15;
    const int halfb  = ((lane >> 4) & 1) * 16;

    const int8_t* srcA0 = g_Xq0  + (size_t)m0 * DIN;
    const int8_t* srcA1 = g_Xq1  + (size_t)m0 * DIN;
    const int8_t* srcB0 = g_W1q0 + (size_t)n0 * DIN;
    const int8_t* srcB1 = g_W1q1 + (size_t)n0 * DIN;
    const int8_t* srcB2 = g_W3q0 + (size_t)n0 * DIN;
    const int8_t* srcB3 = g_W3q1 + (size_t)n0 * DIN;

    int accH1[2][4][4], accL1[2][4][4], accH2[2][4][4], accL2[2][4][4];
#pragma unroll
    for (int m = 0; m < 2; m++)
#pragma unroll
        for (int nf = 0; nf < 4; nf++)
#pragma unroll
            for (int j = 0; j < 4; j++) {
                accH1[m][nf][j] = 0; accL1[m][nf][j] = 0;
                accH2[m][nf][j] = 0; accL2[m][nf][j] = 0;
            }

    auto load_chunk = [&](int c, int buf) {
        const int k0 = c * 64;
        const uint32_t bb = sb + (uint32_t)buf * 32768;
#pragma unroll
        for (int i = 0; i < 2; i++) {      // A tiles: 512 cp16 each, 2/thread
            int s = tid + i * 256;
            int row = s >> 2, v = s & 3;
            uint32_t so = SWZ64(row * 64 + v * 16);
            size_t go = (size_t)row * DIN + k0 + v * 16;
            cp16(bb + so,        srcA0 + go);
            cp16(bb + 8192 + so, srcA1 + go);
        }
        {   // B tiles: 64 rows x 4 slots = 256 cp16 each, 1/thread/tile
            int row = tid >> 2, v = tid & 3;
            uint32_t so = SWZ64(row * 64 + v * 16);
            size_t go = (size_t)row * DIN + k0 + v * 16;
            cp16(bb + 16384 + so,         srcB0 + go);
            cp16(bb + 16384 + 4096 + so,  srcB1 + go);
            cp16(bb + 16384 + 8192 + so,  srcB2 + go);
            cp16(bb + 16384 + 12288 + so, srcB3 + go);
        }
    };

    load_chunk(0, 0); CP_COMMIT();
    load_chunk(1, 1); CP_COMMIT();
    const int NCH = DIN / 64;   // 8
    for (int c = 0; c < NCH; c++) {
        if (c == NCH - 1) { CP_WAIT0(); } else { CP_WAIT1(); }
        __syncthreads();
        if (c + 2 < NCH) { load_chunk(c + 2, (c + 2) % 3); CP_COMMIT(); }

        const uint32_t bb = sb + (uint32_t)((c % 3) * 32768);
#pragma unroll
        for (int ks = 0; ks < 2; ks++) {
            const int kb = ks * 32;
            uint32_t Aq0[2][4], Aq1[2][4];
#pragma unroll
            for (int m = 0; m < 2; m++) {
                uint32_t off = SWZ64((warp_m * 32 + m * 16 + r_lane) * 64 + kb + halfb);
                ldsm4(Aq0[m], bb + off);
                ldsm4(Aq1[m], bb + 8192 + off);
            }
            uint32_t B1q0[2][4], B1q1[2][4], B2q0[2][4], B2q1[2][4];
#pragma unroll
            for (int nb = 0; nb < 2; nb++) {
                uint32_t offB = SWZ64((warp_n * 32 + nb * 16 + r_lane) * 64 + kb + halfb);
                ldsm4(B1q0[nb], bb + 16384 + offB);
                ldsm4(B1q1[nb], bb + 16384 + 4096 + offB);
                ldsm4(B2q0[nb], bb + 16384 + 8192 + offB);
                ldsm4(B2q1[nb], bb + 16384 + 12288 + offB);
            }
#pragma unroll
            for (int nb = 0; nb < 2; nb++)
#pragma unroll
                for (int e = 0; e < 2; e++) {
                    const int nf = nb * 2 + e;
#pragma unroll
                    for (int m = 0; m < 2; m++) {
                        imma(accH1[m][nf], Aq0[m], B1q0[nb][e], B1q0[nb][2 + e]);
                        imma(accL1[m][nf], Aq0[m], B1q1[nb][e], B1q1[nb][2 + e]);
                        imma(accL1[m][nf], Aq1[m], B1q0[nb][e], B1q0[nb][2 + e]);
                        imma(accH2[m][nf], Aq0[m], B2q0[nb][e], B2q0[nb][2 + e]);
                        imma(accL2[m][nf], Aq0[m], B2q1[nb][e], B2q1[nb][2 + e]);
                        imma(accL2[m][nf], Aq1[m], B2q0[nb][e], B2q0[nb][2 + e]);
                    }
                }
        }
    }

    // ---- epilogue: scales, activations, int8 2-level quant, staged via smem ----
    __syncthreads();
    const int g = lane >> 2, t4 = lane & 3;
    float sx[2][2];
#pragma unroll
    for (int m = 0; m < 2; m++)
#pragma unroll
        for (int h = 0; h < 2; h++)
            sx[m][h] = g_sX[m0 + warp_m * 32 + m * 16 + g + h * 8];

#pragma unroll
    for (int m = 0; m < 2; m++)
#pragma unroll
        for (int nf = 0; nf < 4; nf++) {
            const int cl = warp_n * 32 + nf * 8 + t4 * 2;
            // FIX (R9 bug): weight dequant scale is colmax/127, not raw colmax
            const float sw1a = g_sW1[n0 + cl] * INV127, sw1b = g_sW1[n0 + cl + 1] * INV127;
            const float sw3a = g_sW3[n0 + cl] * INV127, sw3b = g_sW3[n0 + cl + 1] * INV127;
            const float ba = __ldg(bias + n0 + cl), bb2 = __ldg(bias + n0 + cl + 1);
#pragma unroll
            for (int h = 0; h < 2; h++) {
                const int rl = warp_m * 32 + m * 16 + g + h * 8;
                const float s = sx[m][h];
                float v1a = s * sw1a * ((float)accH1[m][nf][h * 2 + 0] + INV128 * (float)accL1[m][nf][h * 2 + 0]);
                float v1b = s * sw1b * ((float)accH1[m][nf][h * 2 + 1] + INV128 * (float)accL1[m][nf][h * 2 + 1]);
                float v2a = s * sw3a * ((float)accH2[m][nf][h * 2 + 0] + INV128 * (float)accL2[m][nf][h * 2 + 0]);
                float v2b = s * sw3b * ((float)accH2[m][nf][h * 2 + 1] + INV128 * (float)accL2[m][nf][h * 2 + 1]);
                float h1a = __cosf(v1a * S_IN + ba);
                float h1b = __cosf(v1b * S_IN + bb2);
                float h2a = 1.f / (1.f + __expf(-v2a * S_IN));
                float h2b = 1.f / (1.f + __expf(-v2b * S_IN));

                float t1a = h1a * 127.f, t1b = h1b * 127.f;
                float t2a = h2a * 127.f, t2b = h2b * 127.f;
                int q1a = __float2int_rn(t1a), q1b = __float2int_rn(t1b);
                int q2a = __float2int_rn(t2a), q2b = __float2int_rn(t2b);
                char2 c1q0 = make_char2((char)q1a, (char)q1b);
                char2 c1q1 = make_char2((char)__float2int_rn((t1a - q1a) * 128.f),
                                        (char)__float2int_rn((t1b - q1b) * 128.f));
                char2 c2q0 = make_char2((char)q2a, (char)q2b);
                char2 c2q1 = make_char2((char)__float2int_rn((t2a - q2a) * 128.f),
                                        (char)__float2int_rn((t2b - q2b) * 128.f));
                uint32_t off = (uint32_t)rl * 80 + cl;
                *(char2*)(smem + 0 * 10240 + off) = c1q0;
                *(char2*)(smem + 1 * 10240 + off) = c1q1;
                *(char2*)(smem + 2 * 10240 + off) = c2q0;
                *(char2*)(smem + 3 * 10240 + off) = c2q1;
            }
        }
    __syncthreads();

    {   // coalesced store: 128 rows x 64B per plane, 2 chunks/thread/plane
        int8_t* o0 = g_H1q0; int8_t* o1 = g_H1q1;
        int8_t* o2 = g_H2q0; int8_t* o3 = g_H2q1;
#pragma unroll
        for (int i = 0; i < 2; i++) {
            int s = tid + i * 256;
            int row = s >> 2, colc = (s & 3) * 16;
            uint32_t so = (uint32_t)row * 80 + colc;
            size_t go = (size_t)(m0 + row) * HID + n0 + colc;
            *(uint4*)(o0 + go) = *(const uint4*)(smem + 0 * 10240 + so);
            *(uint4*)(o1 + go) = *(const uint4*)(smem + 1 * 10240 + so);
            *(uint4*)(o2 + go) = *(const uint4*)(smem + 2 * 10240 + so);
            *(uint4*)(o3 + go) = *(const uint4*)(smem + 3 * 10240 + so);
        }
    }
}

// ---------------- stage 2: fused dual int8 GEMM (K=2048) + product ----------------
// grid (DOUT/64=8, 512), 256 threads; buffer = A0..A3 (8KB) + B0..B3 (4KB) = 48KB
#define S2_SMEM (3 * 49152)
__global__ __launch_bounds__(256, 1) void stage2_kernel(float* __restrict__ out) {
    extern __shared__ char smem[];
    const uint32_t sb = smem_u32(smem);
    const int tid = threadIdx.x, wid = tid >> 5, lane = tid & 31;
    const int warp_m = wid & 3, warp_n = wid >> 2;
    const int m0 = blockIdx.y * 128, c0 = blockIdx.x * 64;
    const int r_lane = lane & 15;
    const int halfb  = ((lane >> 4) & 1) * 16;

    const int8_t* srcA0 = g_H1q0 + (size_t)m0 * HID;
    const int8_t* srcA1 = g_H1q1 + (size_t)m0 * HID;
    const int8_t* srcA2 = g_H2q0 + (size_t)m0 * HID;
    const int8_t* srcA3 = g_H2q1 + (size_t)m0 * HID;
    const int8_t* srcB0 = g_W2q0 + (size_t)c0 * HID;
    const int8_t* srcB1 = g_W2q1 + (size_t)c0 * HID;
    const int8_t* srcB2 = g_W4q0 + (size_t)c0 * HID;
    const int8_t* srcB3 = g_W4q1 + (size_t)c0 * HID;

    int accH1[2][4][4], accL1[2][4][4], accH2[2][4][4], accL2[2][4][4];
#pragma unroll
    for (int m = 0; m < 2; m++)
#pragma unroll
        for (int nf = 0; nf < 4; nf++)
#pragma unroll
            for (int j = 0; j < 4; j++) {
                accH1[m][nf][j] = 0; accL1[m][nf][j] = 0;
                accH2[m][nf][j] = 0; accL2[m][nf][j] = 0;
            }

    auto load_chunk = [&](int c, int buf) {
        const int k0 = c * 64;
        const uint32_t bb = sb + (uint32_t)buf * 49152;
#pragma unroll
        for (int i = 0; i < 2; i++) {      // A tiles: 512 cp16 each, 2/thread
            int s = tid + i * 256;
            int row = s >> 2, v = s & 3;
            uint32_t so = SWZ64(row * 64 + v * 16);
            size_t go = (size_t)row * HID + k0 + v * 16;
            cp16(bb + so,         srcA0 + go);
            cp16(bb + 8192 + so,  srcA1 + go);
            cp16(bb + 16384 + so, srcA2 + go);
            cp16(bb + 24576 + so, srcA3 + go);
        }
        {   // B tiles: 256 cp16 each, 1/thread/tile
            int row = tid >> 2, v = tid & 3;
            uint32_t so = SWZ64(row * 64 + v * 16);
            size_t go = (size_t)row * HID + k0 + v * 16;
            cp16(bb + 32768 + so,         srcB0 + go);
            cp16(bb + 32768 + 4096 + so,  srcB1 + go);
            cp16(bb + 32768 + 8192 + so,  srcB2 + go);
            cp16(bb + 32768 + 12288 + so, srcB3 + go);
        }
    };

    load_chunk(0, 0); CP_COMMIT();
    load_chunk(1, 1); CP_COMMIT();
    const int NCH = HID / 64;   // 32
    for (int c = 0; c < NCH; c++) {
        if (c == NCH - 1) { CP_WAIT0(); } else { CP_WAIT1(); }
        __syncthreads();
        if (c + 2 < NCH) { load_chunk(c + 2, (c + 2) % 3); CP_COMMIT(); }

        const uint32_t bb = sb + (uint32_t)((c % 3) * 49152);
#pragma unroll
        for (int ks = 0; ks < 2; ks++) {
            const int kb = ks * 32;
            uint32_t A1q0[2][4], A1q1[2][4], A2q0[2][4], A2q1[2][4];
#pragma unroll
            for (int m = 0; m < 2; m++) {
                uint32_t off = SWZ64((warp_m * 32 + m * 16 + r_lane) * 64 + kb + halfb);
                ldsm4(A1q0[m], bb + off);
                ldsm4(A1q1[m], bb + 8192 + off);
                ldsm4(A2q0[m], bb + 16384 + off);
                ldsm4(A2q1[m], bb + 24576 + off);
            }
            uint32_t B1q0[2][4], B1q1[2][4], B2q0[2][4], B2q1[2][4];
#pragma unroll
            for (int nb = 0; nb < 2; nb++) {
                uint32_t offB = SWZ64((warp_n * 32 + nb * 16 + r_lane) * 64 + kb + halfb);
                ldsm4(B1q0[nb], bb + 32768 + offB);
                ldsm4(B1q1[nb], bb + 32768 + 4096 + offB);
                ldsm4(B2q0[nb], bb + 32768 + 8192 + offB);
                ldsm4(B2q1[nb], bb + 32768 + 12288 + offB);
            }
#pragma unroll
            for (int nb = 0; nb < 2; nb++)
#pragma unroll
                for (int e = 0; e < 2; e++) {
                    const int nf = nb * 2 + e;
#pragma unroll
                    for (int m = 0; m < 2; m++) {
                        imma(accH1[m][nf], A1q0[m], B1q0[nb][e], B1q0[nb][2 + e]);
                        imma(accL1[m][nf], A1q0[m], B1q1[nb][e], B1q1[nb][2 + e]);
                        imma(accL1[m][nf], A1q1[m], B1q0[nb][e], B1q0[nb][2 + e]);
                        imma(accH2[m][nf], A2q0[m], B2q0[nb][e], B2q0[nb][2 + e]);
                        imma(accL2[m][nf], A2q0[m], B2q1[nb][e], B2q1[nb][2 + e]);
                        imma(accL2[m][nf], A2q1[m], B2q0[nb][e], B2q0[nb][2 + e]);
                    }
                }
        }
    }

    // epilogue: out = val1 * val2 * S_H2
    const int g = lane >> 2, t4 = lane & 3;
#pragma unroll
    for (int m = 0; m < 2; m++)
#pragma unroll
        for (int nf = 0; nf < 4; nf++) {
            const int cl = warp_n * 32 + nf * 8 + t4 * 2;
            // FIX (R9 bug): weight scale colmax/127 AND hidden scale 1/127 => INV127SQ
            const float sw2a = g_sW2[c0 + cl] * INV127SQ, sw2b = g_sW2[c0 + cl + 1] * INV127SQ;
            const float sw4a = g_sW4[c0 + cl] * INV127SQ, sw4b = g_sW4[c0 + cl + 1] * INV127SQ;
#pragma unroll
            for (int h = 0; h < 2; h++) {
                const int row = m0 + warp_m * 32 + m * 16 + g + h * 8;
                float v1a = sw2a * ((float)accH1[m][nf][h * 2 + 0] + INV128 * (float)accL1[m][nf][h * 2 + 0]);
                float v1b = sw2b * ((float)accH1[m][nf][h * 2 + 1] + INV128 * (float)accL1[m][nf][h * 2 + 1]);
                float v2a = sw4a * ((float)accH2[m][nf][h * 2 + 0] + INV128 * (float)accL2[m][nf][h * 2 + 0]);
                float v2b = sw4b * ((float)accH2[m][nf][h * 2 + 1] + INV128 * (float)accL2[m][nf][h * 2 + 1]);
                float2 o;
                o.x = v1a * v2a * S_H2;
                o.y = v1b * v2b * S_H2;
                *(float2*)(out + (size_t)row * DOUT + c0 + cl) = o;
            }
        }
}

// ---------------- launch ----------------
// Inputs (metadata order): x, W_rff1, bias, W_rff2, W_sig1, W_sig2
extern "C" void kernel_launch(void* const* d_in, const int* in_sizes, int n_in,
                              void* d_out, int out_size)
{
    (void)in_sizes; (void)n_in; (void)out_size;
    const float* x    = (const float*)d_in[0];
    const float* W1   = (const float*)d_in[1];
    const float* bias = (const float*)d_in[2];
    const float* W2   = (const float*)d_in[3];
    const float* W3   = (const float*)d_in[4];
    const float* W4   = (const float*)d_in[5];
    float* out = (float*)d_out;

    cudaFuncSetAttribute(stage1_kernel, cudaFuncAttributeMaxDynamicSharedMemorySize, S1_SMEM);
    cudaFuncSetAttribute(stage2_kernel, cudaFuncAttributeMaxDynamicSharedMemorySize, S2_SMEM);

    zero_scales_kernel<<<HID / 256, 256>>>();
    quant_x_kernel<<<NROWS / 8, 256>>>(x);
    wcolmax_kernel<<<dim3(HID / 256, 8),  256>>>(W1, 0, DIN, HID);
    wcolmax_kernel<<<dim3(HID / 256, 8),  256>>>(W3, 1, DIN, HID);
    wcolmax_kernel<<<dim3(DOUT / 256, 8), 256>>>(W2, 2, HID, DOUT);
    wcolmax_kernel<<<dim3(DOUT / 256, 8), 256>>>(W4, 3, HID, DOUT);
    wquant_kernel<<<dim3(DIN / 32, HID / 32),  dim3(32, 8)>>>(W1, 0, DIN, HID);
    wquant_kernel<<<dim3(DIN / 32, HID / 32),  dim3(32, 8)>>>(W3, 1, DIN, HID);
    wquant_kernel<<<dim3(HID / 32, DOUT / 32), dim3(32, 8)>>>(W2, 2, HID, DOUT);
    wquant_kernel<<<dim3(HID / 32, DOUT / 32), dim3(32, 8)>>>(W4, 3, HID, DOUT);

    stage1_kernel<<<dim3(HID / 64, NROWS / 128), 256, S1_SMEM>>>(bias);
    stage2_kernel<<<dim3(DOUT / 64, NROWS / 128), 256, S2_SMEM>>>(out);
}

// round 11
// speedup vs baseline: 1.9374x; 1.1694x over previous
#include <cuda_runtime.h>
#include <cstdint>
#include <math.h>

// ---------------- problem constants ----------------
#define NROWS 65536
#define DIN   512
#define HID   2048
#define DOUT  512
#define S_IN   0.04419417382415922f   // 1/sqrt(512)
#define S_H2   4.8828125e-4f          // (1/sqrt(2048))^2
#define INV128 0.0078125f
#define INV127 0.007874015748031496f
#define INV127SQ 6.200012400024800e-5f  // (1/127)^2

// ---------------- scratch (static __device__, allowed) ----------------
__device__ __align__(256) int8_t g_Xq0[(size_t)NROWS * DIN];
__device__ __align__(256) int8_t g_Xq1[(size_t)NROWS * DIN];
__device__ float g_sX[NROWS];
__device__ __align__(256) int8_t g_W1q0[(size_t)HID * DIN];   // W1^T [H][DIN]
__device__ __align__(256) int8_t g_W1q1[(size_t)HID * DIN];
__device__ __align__(256) int8_t g_W3q0[(size_t)HID * DIN];
__device__ __align__(256) int8_t g_W3q1[(size_t)HID * DIN];
__device__ __align__(256) int8_t g_W2q0[(size_t)DOUT * HID];  // W2^T [DOUT][H]
__device__ __align__(256) int8_t g_W2q1[(size_t)DOUT * HID];
__device__ __align__(256) int8_t g_W4q0[(size_t)DOUT * HID];
__device__ __align__(256) int8_t g_W4q1[(size_t)DOUT * HID];
__device__ float g_sW1[HID];
__device__ float g_sW3[HID];
__device__ float g_sW2[DOUT];
__device__ float g_sW4[DOUT];
__device__ __align__(256) int8_t g_H1q0[(size_t)NROWS * HID];
__device__ __align__(256) int8_t g_H1q1[(size_t)NROWS * HID];
__device__ __align__(256) int8_t g_H2q0[(size_t)NROWS * HID];
__device__ __align__(256) int8_t g_H2q1[(size_t)NROWS * HID];
__device__ __align__(256) float g_P1[(size_t)NROWS * DOUT];
__device__ __align__(256) float g_P2[(size_t)NROWS * DOUT];

// ---------------- helpers ----------------
__device__ __forceinline__ uint32_t smem_u32(const void* p) {
    uint32_t a;
    asm("{ .reg .u64 t; cvta.to.shared.u64 t, %1; cvt.u32.u64 %0, t; }" : "=r"(a) : "l"(p));
    return a;
}
__device__ __forceinline__ void cp16(uint32_t d, const void* s) {
    asm volatile("cp.async.cg.shared.global [%0], [%1], 16;" :: "r"(d), "l"(s));
}
#define CP_COMMIT() asm volatile("cp.async.commit_group;" ::: "memory")
#define CP_WAIT1()  asm volatile("cp.async.wait_group 1;" ::: "memory")
#define CP_WAIT0()  asm volatile("cp.async.wait_group 0;" ::: "memory")

__device__ __forceinline__ void ldsm4(uint32_t (&r)[4], uint32_t addr) {
    asm volatile("ldmatrix.sync.aligned.m8n8.x4.shared.b16 {%0,%1,%2,%3}, [%4];"
                 : "=r"(r[0]), "=r"(r[1]), "=r"(r[2]), "=r"(r[3]) : "r"(addr));
}
// int8 MMA: m16n8k32, s8 x s8 -> s32
__device__ __forceinline__ void imma(int (&d)[4], const uint32_t (&a)[4],
                                     uint32_t b0, uint32_t b1) {
    asm volatile(
        "mma.sync.aligned.m16n8k32.row.col.s32.s8.s8.s32 "
        "{%0,%1,%2,%3}, {%4,%5,%6,%7}, {%8,%9}, {%0,%1,%2,%3};"
        : "+r"(d[0]), "+r"(d[1]), "+r"(d[2]), "+r"(d[3])
        : "r"(a[0]), "r"(a[1]), "r"(a[2]), "r"(a[3]), "r"(b0), "r"(b1));
}

#define SWZ64(o) ((o) ^ (((o) >> 3) & 0x30))

// ---------------- L0: quantize X + zero weight scales ----------------
__global__ void quant_x_kernel(const float* __restrict__ x) {
    if (blockIdx.x == 0) {
        for (int i = threadIdx.x; i < HID; i += 256) { g_sW1[i] = 0.f; g_sW3[i] = 0.f; }
        for (int i = threadIdx.x; i < DOUT; i += 256) { g_sW2[i] = 0.f; g_sW4[i] = 0.f; }
    }
    int wrow = blockIdx.x * 8 + (threadIdx.x >> 5);
    int lane = threadIdx.x & 31;
    const float4* xr = (const float4*)(x + (size_t)wrow * DIN);
    float4 v[4];
    float m = 0.f;
#pragma unroll
    for (int i = 0; i < 4; i++) {
        v[i] = xr[lane + i * 32];
        m = fmaxf(m, fmaxf(fmaxf(fabsf(v[i].x), fabsf(v[i].y)),
                           fmaxf(fabsf(v[i].z), fabsf(v[i].w))));
    }
#pragma unroll
    for (int o = 16; o; o >>= 1) m = fmaxf(m, __shfl_xor_sync(0xFFFFFFFFu, m, o));
    m = fmaxf(m, 1e-20f);
    float inv = 127.f / m;
    if (lane == 0) g_sX[wrow] = m * INV127;
#pragma unroll
    for (int i = 0; i < 4; i++) {
        float t0 = v[i].x * inv, t1 = v[i].y * inv, t2 = v[i].z * inv, t3 = v[i].w * inv;
        int a0 = __float2int_rn(t0), a1 = __float2int_rn(t1);
        int a2 = __float2int_rn(t2), a3 = __float2int_rn(t3);
        char4 q0 = make_char4((char)a0, (char)a1, (char)a2, (char)a3);
        char4 q1 = make_char4((char)__float2int_rn((t0 - a0) * 128.f),
                              (char)__float2int_rn((t1 - a1) * 128.f),
                              (char)__float2int_rn((t2 - a2) * 128.f),
                              (char)__float2int_rn((t3 - a3) * 128.f));
        ((char4*)g_Xq0)[(size_t)wrow * (DIN / 4) + lane + i * 32] = q0;
        ((char4*)g_Xq1)[(size_t)wrow * (DIN / 4) + lane + i * 32] = q1;
    }
}

// ---------------- L1/L2: weight column max (pairs share shape, z picks one) ----
__global__ void wcolmax13_kernel(const float* __restrict__ W1, const float* __restrict__ W3) {
    const float* in = blockIdx.z ? W3 : W1;
    float* sc = blockIdx.z ? g_sW3 : g_sW1;
    int n = blockIdx.x * 256 + threadIdx.x;
    const float* p = in + (size_t)blockIdx.y * (DIN / 8) * HID + n;
    float m = 0.f;
#pragma unroll 8
    for (int k = 0; k < DIN / 8; k++) m = fmaxf(m, fabsf(p[(size_t)k * HID]));
    atomicMax((unsigned int*)&sc[n], __float_as_uint(m));
}
__global__ void wcolmax24_kernel(const float* __restrict__ W2, const float* __restrict__ W4) {
    const float* in = blockIdx.z ? W4 : W2;
    float* sc = blockIdx.z ? g_sW4 : g_sW2;
    int n = blockIdx.x * 256 + threadIdx.x;
    const float* p = in + (size_t)blockIdx.y * (HID / 8) * DOUT + n;
    float m = 0.f;
#pragma unroll 8
    for (int k = 0; k < HID / 8; k++) m = fmaxf(m, fabsf(p[(size_t)k * DOUT]));
    atomicMax((unsigned int*)&sc[n], __float_as_uint(m));
}

// ---------------- L3/L4: transpose-quantize ----------------
__global__ void wquant13_kernel(const float* __restrict__ W1, const float* __restrict__ W3) {
    const float* in = blockIdx.z ? W3 : W1;
    int8_t* q0o = blockIdx.z ? g_W3q0 : g_W1q0;
    int8_t* q1o = blockIdx.z ? g_W3q1 : g_W1q1;
    const float* sc = blockIdx.z ? g_sW3 : g_sW1;
    __shared__ float t[32][33];
    int k0 = blockIdx.x * 32, n0 = blockIdx.y * 32;
    int tx = threadIdx.x, ty = threadIdx.y;
#pragma unroll
    for (int i = 0; i < 4; i++)
        t[ty + i * 8][tx] = in[(size_t)(k0 + ty + i * 8) * HID + n0 + tx];
    __syncthreads();
#pragma unroll
    for (int i = 0; i < 4; i++) {
        int n = n0 + ty + i * 8;
        float inv = 127.f / fmaxf(sc[n], 1e-20f);
        float v = t[tx][ty + i * 8] * inv;
        int a = __float2int_rn(v);
        q0o[(size_t)n * DIN + k0 + tx] = (int8_t)a;
        q1o[(size_t)n * DIN + k0 + tx] = (int8_t)__float2int_rn((v - a) * 128.f);
    }
}
__global__ void wquant24_kernel(const float* __restrict__ W2, const float* __restrict__ W4) {
    const float* in = blockIdx.z ? W4 : W2;
    int8_t* q0o = blockIdx.z ? g_W4q0 : g_W2q0;
    int8_t* q1o = blockIdx.z ? g_W4q1 : g_W2q1;
    const float* sc = blockIdx.z ? g_sW4 : g_sW2;
    __shared__ float t[32][33];
    int k0 = blockIdx.x * 32, n0 = blockIdx.y * 32;
    int tx = threadIdx.x, ty = threadIdx.y;
#pragma unroll
    for (int i = 0; i < 4; i++)
        t[ty + i * 8][tx] = in[(size_t)(k0 + ty + i * 8) * DOUT + n0 + tx];
    __syncthreads();
#pragma unroll
    for (int i = 0; i < 4; i++) {
        int n = n0 + ty + i * 8;
        float inv = 127.f / fmaxf(sc[n], 1e-20f);
        float v = t[tx][ty + i * 8] * inv;
        int a = __float2int_rn(v);
        q0o[(size_t)n * HID + k0 + tx] = (int8_t)a;
        q1o[(size_t)n * HID + k0 + tx] = (int8_t)__float2int_rn((v - a) * 128.f);
    }
}

// ---------------- stage 1: single-branch int8 GEMM (K=512) + activation ------
// grid (HID/64=32, NROWS/128=512, 2 branches), 256 threads, 2 CTAs/SM target.
// buffer = Aq0,Aq1 (8KB each) + Bq0,Bq1 (4KB each) = 24KB; 3 buffers = 72KB
#define BUF1 24576
#define S1_SMEM (3 * BUF1)
__global__ __launch_bounds__(256, 2) void stage1_kernel(const float* __restrict__ bias) {
    extern __shared__ char smem[];
    const uint32_t sb = smem_u32(smem);
    const int tid = threadIdx.x, wid = tid >> 5, lane = tid & 31;
    const int warp_m = wid & 3, warp_n = wid >> 2;
    const int m0 = blockIdx.y * 128, n0 = blockIdx.x * 64;
    const int z = blockIdx.z;
    const int r_lane = lane & 15;
    const int halfb  = ((lane >> 4) & 1) * 16;

    const int8_t* srcA0 = g_Xq0 + (size_t)m0 * DIN;
    const int8_t* srcA1 = g_Xq1 + (size_t)m0 * DIN;
    const int8_t* srcB0 = (z ? g_W3q0 : g_W1q0) + (size_t)n0 * DIN;
    const int8_t* srcB1 = (z ? g_W3q1 : g_W1q1) + (size_t)n0 * DIN;
    const float* sw = z ? g_sW3 : g_sW1;

    int accH[2][4][4], accL[2][4][4];
#pragma unroll
    for (int m = 0; m < 2; m++)
#pragma unroll
        for (int nf = 0; nf < 4; nf++)
#pragma unroll
            for (int j = 0; j < 4; j++) { accH[m][nf][j] = 0; accL[m][nf][j] = 0; }

    auto load_chunk = [&](int c, int buf) {
        const int k0 = c * 64;
        const uint32_t bb = sb + (uint32_t)buf * BUF1;
#pragma unroll
        for (int i = 0; i < 2; i++) {      // A tiles: 512 cp16 each, 2/thread
            int s = tid + i * 256;
            int row = s >> 2, v = s & 3;
            uint32_t so = SWZ64(row * 64 + v * 16);
            size_t go = (size_t)row * DIN + k0 + v * 16;
            cp16(bb + so,        srcA0 + go);
            cp16(bb + 8192 + so, srcA1 + go);
        }
        {   // B tiles: 256 cp16 each, 1/thread
            int row = tid >> 2, v = tid & 3;
            uint32_t so = SWZ64(row * 64 + v * 16);
            size_t go = (size_t)row * DIN + k0 + v * 16;
            cp16(bb + 16384 + so, srcB0 + go);
            cp16(bb + 20480 + so, srcB1 + go);
        }
    };

    load_chunk(0, 0); CP_COMMIT();
    load_chunk(1, 1); CP_COMMIT();
    const int NCH = DIN / 64;   // 8
    for (int c = 0; c < NCH; c++) {
        if (c == NCH - 1) { CP_WAIT0(); } else { CP_WAIT1(); }
        __syncthreads();
        if (c + 2 < NCH) { load_chunk(c + 2, (c + 2) % 3); CP_COMMIT(); }

        const uint32_t bb = sb + (uint32_t)((c % 3) * BUF1);
#pragma unroll
        for (int ks = 0; ks < 2; ks++) {
            const int kb = ks * 32;
            uint32_t Aq0[2][4], Aq1[2][4];
#pragma unroll
            for (int m = 0; m < 2; m++) {
                uint32_t off = SWZ64((warp_m * 32 + m * 16 + r_lane) * 64 + kb + halfb);
                ldsm4(Aq0[m], bb + off);
                ldsm4(Aq1[m], bb + 8192 + off);
            }
            uint32_t Bq0[2][4], Bq1[2][4];
#pragma unroll
            for (int nb = 0; nb < 2; nb++) {
                uint32_t offB = SWZ64((warp_n * 32 + nb * 16 + r_lane) * 64 + kb + halfb);
                ldsm4(Bq0[nb], bb + 16384 + offB);
                ldsm4(Bq1[nb], bb + 20480 + offB);
            }
#pragma unroll
            for (int nb = 0; nb < 2; nb++)
#pragma unroll
                for (int e = 0; e < 2; e++) {
                    const int nf = nb * 2 + e;
#pragma unroll
                    for (int m = 0; m < 2; m++) {
                        imma(accH[m][nf], Aq0[m], Bq0[nb][e], Bq0[nb][2 + e]);
                        imma(accL[m][nf], Aq0[m], Bq1[nb][e], Bq1[nb][2 + e]);
                        imma(accL[m][nf], Aq1[m], Bq0[nb][e], Bq0[nb][2 + e]);
                    }
                }
        }
    }

    // ---- epilogue: dequant, activation, 2-level int8 quant, staged via smem ----
    __syncthreads();
    const int g = lane >> 2, t4 = lane & 3;
    float sx[2][2];
#pragma unroll
    for (int m = 0; m < 2; m++)
#pragma unroll
        for (int h = 0; h < 2; h++)
            sx[m][h] = g_sX[m0 + warp_m * 32 + m * 16 + g + h * 8];

#pragma unroll
    for (int m = 0; m < 2; m++)
#pragma unroll
        for (int nf = 0; nf < 4; nf++) {
            const int cl = warp_n * 32 + nf * 8 + t4 * 2;
            const float swa = sw[n0 + cl] * INV127, swb = sw[n0 + cl + 1] * INV127;
            float ba = 0.f, bb2 = 0.f;
            if (z == 0) { ba = __ldg(bias + n0 + cl); bb2 = __ldg(bias + n0 + cl + 1); }
#pragma unroll
            for (int h = 0; h < 2; h++) {
                const int rl = warp_m * 32 + m * 16 + g + h * 8;
                const float s = sx[m][h];
                float va = s * swa * ((float)accH[m][nf][h * 2 + 0] + INV128 * (float)accL[m][nf][h * 2 + 0]);
                float vb = s * swb * ((float)accH[m][nf][h * 2 + 1] + INV128 * (float)accL[m][nf][h * 2 + 1]);
                float ha, hb;
                if (z == 0) {
                    ha = __cosf(va * S_IN + ba);
                    hb = __cosf(vb * S_IN + bb2);
                } else {
                    ha = 1.f / (1.f + __expf(-va * S_IN));
                    hb = 1.f / (1.f + __expf(-vb * S_IN));
                }
                float ta = ha * 127.f, tb = hb * 127.f;
                int qa = __float2int_rn(ta), qb = __float2int_rn(tb);
                char2 cq0 = make_char2((char)qa, (char)qb);
                char2 cq1 = make_char2((char)__float2int_rn((ta - qa) * 128.f),
                                       (char)__float2int_rn((tb - qb) * 128.f));
                uint32_t off = (uint32_t)rl * 80 + cl;
                *(char2*)(smem + off)         = cq0;
                *(char2*)(smem + 10240 + off) = cq1;
            }
        }
    __syncthreads();

    {   // coalesced store: 2 planes, 2 chunks/thread each
        int8_t* o0 = z ? g_H2q0 : g_H1q0;
        int8_t* o1 = z ? g_H2q1 : g_H1q1;
#pragma unroll
        for (int i = 0; i < 2; i++) {
            int s = tid + i * 256;
            int row = s >> 2, colc = (s & 3) * 16;
            uint32_t so = (uint32_t)row * 80 + colc;
            size_t go = (size_t)(m0 + row) * HID + n0 + colc;
            *(uint4*)(o0 + go) = *(const uint4*)(smem + so);
            *(uint4*)(o1 + go) = *(const uint4*)(smem + 10240 + so);
        }
    }
}

// ---------------- stage 2: single-branch int8 GEMM (K=2048) -> P ----------------
// grid (DOUT/64=8, 512, 2 branches), 256 threads, buffer 24KB x3
#define BUF2 24576
#define S2_SMEM (3 * BUF2)
__global__ __launch_bounds__(256, 2) void stage2_kernel() {
    extern __shared__ char smem[];
    const uint32_t sb = smem_u32(smem);
    const int tid = threadIdx.x, wid = tid >> 5, lane = tid & 31;
    const int warp_m = wid & 3, warp_n = wid >> 2;
    const int m0 = blockIdx.y * 128, c0 = blockIdx.x * 64;
    const int z = blockIdx.z;
    const int r_lane = lane & 15;
    const int halfb  = ((lane >> 4) & 1) * 16;

    const int8_t* srcA0 = (z ? g_H2q0 : g_H1q0) + (size_t)m0 * HID;
    const int8_t* srcA1 = (z ? g_H2q1 : g_H1q1) + (size_t)m0 * HID;
    const int8_t* srcB0 = (z ? g_W4q0 : g_W2q0) + (size_t)c0 * HID;
    const int8_t* srcB1 = (z ? g_W4q1 : g_W2q1) + (size_t)c0 * HID;
    const float* sw = z ? g_sW4 : g_sW2;
    float* P = z ? g_P2 : g_P1;

    int accH[2][4][4], accL[2][4][4];
#pragma unroll
    for (int m = 0; m < 2; m++)
#pragma unroll
        for (int nf = 0; nf < 4; nf++)
#pragma unroll
            for (int j = 0; j < 4; j++) { accH[m][nf][j] = 0; accL[m][nf][j] = 0; }

    auto load_chunk = [&](int c, int buf) {
        const int k0 = c * 64;
        const uint32_t bb = sb + (uint32_t)buf * BUF2;
#pragma unroll
        for (int i = 0; i < 2; i++) {
            int s = tid + i * 256;
            int row = s >> 2, v = s & 3;
            uint32_t so = SWZ64(row * 64 + v * 16);
            size_t go = (size_t)row * HID + k0 + v * 16;
            cp16(bb + so,        srcA0 + go);
            cp16(bb + 8192 + so, srcA1 + go);
        }
        {
            int row = tid >> 2, v = tid & 3;
            uint32_t so = SWZ64(row * 64 + v * 16);
            size_t go = (size_t)row * HID + k0 + v * 16;
            cp16(bb + 16384 + so, srcB0 + go);
            cp16(bb + 20480 + so, srcB1 + go);
        }
    };

    load_chunk(0, 0); CP_COMMIT();
    load_chunk(1, 1); CP_COMMIT();
    const int NCH = HID / 64;   // 32
    for (int c = 0; c < NCH; c++) {
        if (c == NCH - 1) { CP_WAIT0(); } else { CP_WAIT1(); }
        __syncthreads();
        if (c + 2 < NCH) { load_chunk(c + 2, (c + 2) % 3); CP_COMMIT(); }

        const uint32_t bb = sb + (uint32_t)((c % 3) * BUF2);
#pragma unroll
        for (int ks = 0; ks < 2; ks++) {
            const int kb = ks * 32;
            uint32_t Aq0[2][4], Aq1[2][4];
#pragma unroll
            for (int m = 0; m < 2; m++) {
                uint32_t off = SWZ64((warp_m * 32 + m * 16 + r_lane) * 64 + kb + halfb);
                ldsm4(Aq0[m], bb + off);
                ldsm4(Aq1[m], bb + 8192 + off);
            }
            uint32_t Bq0[2][4], Bq1[2][4];
#pragma unroll
            for (int nb = 0; nb < 2; nb++) {
                uint32_t offB = SWZ64((warp_n * 32 + nb * 16 + r_lane) * 64 + kb + halfb);
                ldsm4(Bq0[nb], bb + 16384 + offB);
                ldsm4(Bq1[nb], bb + 20480 + offB);
            }
#pragma unroll
            for (int nb = 0; nb < 2; nb++)
#pragma unroll
                for (int e = 0; e < 2; e++) {
                    const int nf = nb * 2 + e;
#pragma unroll
                    for (int m = 0; m < 2; m++) {
                        imma(accH[m][nf], Aq0[m], Bq0[nb][e], Bq0[nb][2 + e]);
                        imma(accL[m][nf], Aq0[m], Bq1[nb][e], Bq1[nb][2 + e]);
                        imma(accL[m][nf], Aq1[m], Bq0[nb][e], Bq0[nb][2 + e]);
                    }
                }
        }
    }

    // epilogue: P = dequantized GEMM value (pre-s_h)
    const int g = lane >> 2, t4 = lane & 3;
#pragma unroll
    for (int m = 0; m < 2; m++)
#pragma unroll
        for (int nf = 0; nf < 4; nf++) {
            const int cl = warp_n * 32 + nf * 8 + t4 * 2;
            const float swa = sw[c0 + cl] * INV127SQ, swb = sw[c0 + cl + 1] * INV127SQ;
#pragma unroll
            for (int h = 0; h < 2; h++) {
                const int row = m0 + warp_m * 32 + m * 16 + g + h * 8;
                float2 o;
                o.x = swa * ((float)accH[m][nf][h * 2 + 0] + INV128 * (float)accL[m][nf][h * 2 + 0]);
                o.y = swb * ((float)accH[m][nf][h * 2 + 1] + INV128 * (float)accL[m][nf][h * 2 + 1]);
                *(float2*)(P + (size_t)row * DOUT + c0 + cl) = o;
            }
        }
}

// ---------------- combine: out = P1*P2*S_H2 ----------------
__global__ void combine_kernel(float* __restrict__ out) {
    size_t i = (size_t)blockIdx.x * 256 + threadIdx.x;
    float4 a = ((const float4*)g_P1)[i];
    float4 b = ((const float4*)g_P2)[i];
    float4 o;
    o.x = a.x * b.x * S_H2;
    o.y = a.y * b.y * S_H2;
    o.z = a.z * b.z * S_H2;
    o.w = a.w * b.w * S_H2;
    ((float4*)out)[i] = o;
}

// ---------------- launch ----------------
// Inputs (metadata order): x, W_rff1, bias, W_rff2, W_sig1, W_sig2
// Exactly 5 prep launches so ncu (-s 5 -c 1) profiles stage1_kernel.
extern "C" void kernel_launch(void* const* d_in, const int* in_sizes, int n_in,
                              void* d_out, int out_size)
{
    (void)in_sizes; (void)n_in; (void)out_size;
    const float* x    = (const float*)d_in[0];
    const float* W1   = (const float*)d_in[1];
    const float* bias = (const float*)d_in[2];
    const float* W2   = (const float*)d_in[3];
    const float* W3   = (const float*)d_in[4];
    const float* W4   = (const float*)d_in[5];
    float* out = (float*)d_out;

    cudaFuncSetAttribute(stage1_kernel, cudaFuncAttributeMaxDynamicSharedMemorySize, S1_SMEM);
    cudaFuncSetAttribute(stage2_kernel, cudaFuncAttributeMaxDynamicSharedMemorySize, S2_SMEM);

    quant_x_kernel<<<NROWS / 8, 256>>>(x);                                  // L0 (+scale zero)
    wcolmax13_kernel<<<dim3(HID / 256, 8, 2),  256>>>(W1, W3);              // L1
    wcolmax24_kernel<<<dim3(DOUT / 256, 8, 2), 256>>>(W2, W4);              // L2
    wquant13_kernel<<<dim3(DIN / 32, HID / 32, 2),  dim3(32, 8)>>>(W1, W3); // L3
    wquant24_kernel<<<dim3(HID / 32, DOUT / 32, 2), dim3(32, 8)>>>(W2, W4); // L4
    stage1_kernel<<<dim3(HID / 64, NROWS / 128, 2), 256, S1_SMEM>>>(bias);  // L5 <- profiled
    stage2_kernel<<<dim3(DOUT / 64, NROWS / 128, 2), 256, S2_SMEM>>>();     // L6
    combine_kernel<<<(NROWS * DOUT / 4) / 256, 256>>>(out);                 // L7
}